// round 5
// baseline (speedup 1.0000x reference)
#include <cuda_runtime.h>

#define Bn   4
#define Cn   256
#define CPn  32
#define Hn   64
#define Wn   64
#define HW   (Hn*Wn)          // 4096
#define BHW  (Bn*HW)          // 16384
#define EPSV 1e-5f

// ---------------- scratch (device globals: no allocation allowed) ----------
__device__ __align__(16) float g_k[BHW*CPn];     // key map  (pixel-major)
__device__ __align__(16) float g_q[BHW*CPn];     // query map
__device__ __align__(16) float g_x[BHW*CPn];     // value map
__device__ __align__(16) float g_pre[BHW*CPn];   // attention output
__device__ __align__(16) float g_y[Bn*Cn*HW];    // conv-f output (channel-major)
__device__ float g_sum[Cn], g_sqs[Cn], g_mean[Cn], g_inv[Cn];

// ---------------- kernel 0: zero the stat accumulators ---------------------
__global__ void zero_stats_kernel() {
    int i = threadIdx.x;
    if (i < Cn) { g_sum[i] = 0.f; g_sqs[i] = 0.f; }
}

// ---------------- kernel 1: km/qm/xm 1x1 convs (256 -> 32), pixel-major ----
__global__ __launch_bounds__(256) void qkx_kernel(
    const float* __restrict__ x,  const float* __restrict__ vessel,
    const float* __restrict__ wk, const float* __restrict__ bk,
    const float* __restrict__ wq, const float* __restrict__ bq,
    const float* __restrict__ wx, const float* __restrict__ bx)
{
    __shared__ float ws[Cn*CPn];          // transposed: ws[c*32+o]
    const int map = blockIdx.y;
    const float* __restrict__ w    = (map == 0) ? wk : (map == 1) ? wq : wx;
    const float* __restrict__ bias = (map == 0) ? bk : (map == 1) ? bq : bx;
    float* __restrict__ out        = (map == 0) ? g_k : (map == 1) ? g_q : g_x;

    const int tid = threadIdx.x;
    for (int i = tid; i < Cn*CPn; i += 256) {      // coalesced read of w[o][c]
        int o = i >> 8, c = i & 255;
        ws[c*CPn + o] = w[i];
    }
    __syncthreads();

    const int p  = blockIdx.x * 256 + tid;         // global pixel
    const int b  = p >> 12, hw = p & 4095;
    const float* __restrict__ xp = x + (size_t)b*Cn*HW + hw;

    float acc[CPn];
#pragma unroll
    for (int o = 0; o < CPn; ++o) acc[o] = 0.f;

    for (int c = 0; c < Cn; ++c) {
        float xv = __ldg(xp + c*HW);
        const float4* w4 = (const float4*)(ws + c*CPn);
#pragma unroll
        for (int j = 0; j < 8; ++j) {
            float4 wv = w4[j];
            acc[4*j+0] += wv.x*xv; acc[4*j+1] += wv.y*xv;
            acc[4*j+2] += wv.z*xv; acc[4*j+3] += wv.w*xv;
        }
    }

    const float scale = (map == 0) ? vessel[p] : 1.f;
    float4* op = (float4*)(out + (size_t)p*CPn);
#pragma unroll
    for (int j = 0; j < 8; ++j) {
        float4 v;
        v.x = (acc[4*j+0] + bias[4*j+0]) * scale;
        v.y = (acc[4*j+1] + bias[4*j+1]) * scale;
        v.z = (acc[4*j+2] + bias[4*j+2]) * scale;
        v.w = (acc[4*j+3] + bias[4*j+3]) * scale;
        op[j] = v;
    }
}

// ---------------- kernel 2: fused 4-scale local attention ------------------
// Nested windows: one 9x9 score pass, one combined-weight 9x9 apply pass.
__global__ __launch_bounds__(256) void attn_kernel()
{
    const int tx = threadIdx.x, ty = threadIdx.y;
    const int x  = blockIdx.x*16 + tx;
    const int y  = blockIdx.y*16 + ty;
    const int b  = blockIdx.z;
    const int p  = (b*Hn + y)*Wn + x;

    const float* __restrict__ kb = g_k + (size_t)b*HW*CPn;
    const float* __restrict__ xb = g_x + (size_t)b*HW*CPn;

    float s[81];
#pragma unroll
    for (int i = 0; i < 81; ++i) s[i] = 0.f;

    // ---- scores: s(dy,dx) = <km[y+dy,x+dx,:], qm[y,x,:]>  (OOB -> 0) ----
#pragma unroll 1
    for (int cc = 0; cc < 4; ++cc) {
        const float4* qp = (const float4*)(g_q + (size_t)p*CPn + cc*8);
        float4 qa = qp[0], qb = qp[1];
#pragma unroll
        for (int iy = 0; iy < 9; ++iy) {
            int yy = y + iy - 4;
            bool yok = (unsigned)yy < (unsigned)Hn;
            const float* rowp = kb + (size_t)(yy*Wn)*CPn + cc*8;
#pragma unroll
            for (int ix = 0; ix < 9; ++ix) {
                int xx = x + ix - 4;
                if (yok && (unsigned)xx < (unsigned)Wn) {
                    const float4* kp = (const float4*)(rowp + (size_t)xx*CPn);
                    float4 a = kp[0], b4 = kp[1];
                    s[iy*9+ix] += a.x*qa.x + a.y*qa.y + a.z*qa.z + a.w*qa.w
                                + b4.x*qb.x + b4.y*qb.y + b4.z*qb.z + b4.w*qb.w;
                }
            }
        }
    }

    // ---- shared-max softmax over nested windows -> combined weights ----
    float m = s[0];
#pragma unroll
    for (int i = 1; i < 81; ++i) m = fmaxf(m, s[i]);

    float S9 = 0.f, S7 = 0.f, S5 = 0.f, S3 = 0.f;
#pragma unroll
    for (int iy = 0; iy < 9; ++iy) {
#pragma unroll
        for (int ix = 0; ix < 9; ++ix) {
            int i = iy*9 + ix;
            float ev = __expf(s[i] - m);
            s[i] = ev;
            S9 += ev;
            if (iy >= 1 && iy <= 7 && ix >= 1 && ix <= 7) S7 += ev;
            if (iy >= 2 && iy <= 6 && ix >= 2 && ix <= 6) S5 += ev;
            if (iy >= 3 && iy <= 5 && ix >= 3 && ix <= 5) S3 += ev;
        }
    }
    const float r9 = 1.f/S9, r7 = 1.f/S7, r5 = 1.f/S5, r3 = 1.f/S3;
#pragma unroll
    for (int iy = 0; iy < 9; ++iy) {
#pragma unroll
        for (int ix = 0; ix < 9; ++ix) {
            int i = iy*9 + ix;
            float cf = r9;
            if (iy >= 1 && iy <= 7 && ix >= 1 && ix <= 7) cf += r7;
            if (iy >= 2 && iy <= 6 && ix >= 2 && ix <= 6) cf += r5;
            if (iy >= 3 && iy <= 5 && ix >= 3 && ix <= 5) cf += r3;
            s[i] *= cf;
        }
    }

    // ---- apply: pre[c] = sum_off wgt(off) * xm[y+dy,x+dx,c] ----
#pragma unroll 1
    for (int cc = 0; cc < 4; ++cc) {
        float acc[8];
#pragma unroll
        for (int j = 0; j < 8; ++j) acc[j] = 0.f;
#pragma unroll
        for (int iy = 0; iy < 9; ++iy) {
            int yy = y + iy - 4;
            bool yok = (unsigned)yy < (unsigned)Hn;
            const float* rowp = xb + (size_t)(yy*Wn)*CPn + cc*8;
#pragma unroll
            for (int ix = 0; ix < 9; ++ix) {
                int xx = x + ix - 4;
                if (yok && (unsigned)xx < (unsigned)Wn) {
                    float wgt = s[iy*9+ix];
                    const float4* xp = (const float4*)(rowp + (size_t)xx*CPn);
                    float4 a = xp[0], b4 = xp[1];
                    acc[0] += wgt*a.x;  acc[1] += wgt*a.y;
                    acc[2] += wgt*a.z;  acc[3] += wgt*a.w;
                    acc[4] += wgt*b4.x; acc[5] += wgt*b4.y;
                    acc[6] += wgt*b4.z; acc[7] += wgt*b4.w;
                }
            }
        }
        float4* op = (float4*)(g_pre + (size_t)p*CPn + cc*8);
        op[0] = make_float4(acc[0], acc[1], acc[2], acc[3]);
        op[1] = make_float4(acc[4], acc[5], acc[6], acc[7]);
    }
}

// ---------------- kernel 3: conv-f (32->256) + BN partial stats ------------
// 512 blocks x 256 threads; thread = output channel, block = 32 pixels.
// Writes y channel-major via padded smem transpose.
__global__ __launch_bounds__(256) void convf_kernel(
    const float* __restrict__ wf, const float* __restrict__ bf)
{
    __shared__ float pre_s[32*CPn];
    __shared__ float y_s[32*257];

    const int tid = threadIdx.x;       // = output channel
    const int p0  = blockIdx.x * 32;   // global pixel base

    float wfr[CPn];
    const float4* wp = (const float4*)(wf + tid*CPn);
#pragma unroll
    for (int j = 0; j < 8; ++j) {
        float4 v = wp[j];
        wfr[4*j+0] = v.x; wfr[4*j+1] = v.y; wfr[4*j+2] = v.z; wfr[4*j+3] = v.w;
    }
    for (int i = tid; i < 32*CPn; i += 256)
        pre_s[i] = g_pre[(size_t)p0*CPn + i];
    __syncthreads();

    const float bfv = bf[tid];
    float sum = 0.f, sq = 0.f;
#pragma unroll 1
    for (int pl = 0; pl < 32; ++pl) {
        const float4* pp = (const float4*)(pre_s + pl*CPn);
        float v = bfv;
#pragma unroll
        for (int j = 0; j < 8; ++j) {
            float4 pv = pp[j];
            v += wfr[4*j+0]*pv.x + wfr[4*j+1]*pv.y
               + wfr[4*j+2]*pv.z + wfr[4*j+3]*pv.w;
        }
        sum += v; sq += v*v;
        y_s[pl*257 + tid] = v;
    }
    atomicAdd(&g_sum[tid], sum);
    atomicAdd(&g_sqs[tid], sq);
    __syncthreads();

    const int b = p0 >> 12, hw0 = p0 & 4095;
    for (int i = tid; i < 32*Cn; i += 256) {
        int c = i >> 5, pl = i & 31;        // lanes sweep pl -> coalesced STG
        g_y[((size_t)(b*Cn + c))*HW + hw0 + pl] = y_s[pl*257 + c];
    }
}

// ---------------- kernel 4: finalize BN stats ------------------------------
__global__ void finalize_stats_kernel() {
    int c = threadIdx.x;
    if (c < Cn) {
        const float invn = 1.f / (float)BHW;
        float mean = g_sum[c] * invn;
        float var  = g_sqs[c] * invn - mean*mean;
        g_mean[c] = mean;
        g_inv[c]  = rsqrtf(var + EPSV);
    }
}

// ---------------- kernel 5: residual + affine (elementwise) ----------------
__global__ __launch_bounds__(256) void out_kernel(
    const float* __restrict__ x, const float* __restrict__ gamma,
    const float* __restrict__ beta, float* __restrict__ out)
{
    int idx = blockIdx.x * 256 + threadIdx.x;   // 4,194,304 total
    int c = (idx >> 12) & 255;
    float yv = g_y[idx];
    out[idx] = x[idx] + gamma[c] * ((yv - g_mean[c]) * g_inv[c]) + beta[c];
}

// ---------------------------------------------------------------------------
extern "C" void kernel_launch(void* const* d_in, const int* in_sizes, int n_in,
                              void* d_out, int out_size)
{
    const float* x      = (const float*)d_in[0];
    const float* vessel = (const float*)d_in[1];
    const float* wk     = (const float*)d_in[2];
    const float* bk     = (const float*)d_in[3];
    const float* wq     = (const float*)d_in[4];
    const float* bq     = (const float*)d_in[5];
    const float* wx     = (const float*)d_in[6];
    const float* bx     = (const float*)d_in[7];
    const float* wf     = (const float*)d_in[8];
    const float* bf     = (const float*)d_in[9];
    const float* gamma  = (const float*)d_in[10];
    const float* beta   = (const float*)d_in[11];
    float* out          = (float*)d_out;

    zero_stats_kernel<<<1, 256>>>();
    qkx_kernel<<<dim3(BHW/256, 3), 256>>>(x, vessel, wk, bk, wq, bq, wx, bx);
    attn_kernel<<<dim3(Wn/16, Hn/16, Bn), dim3(16, 16)>>>();
    convf_kernel<<<BHW/32, 256>>>(wf, bf);
    finalize_stats_kernel<<<1, 256>>>();
    out_kernel<<<Bn*Cn*HW/256, 256>>>(x, gamma, beta, out);
}

// round 8
// speedup vs baseline: 1.7132x; 1.7132x over previous
#include <cuda_runtime.h>

#define Bn   4
#define Cn   256
#define CPn  32
#define Hn   64
#define Wn   64
#define HW   (Hn*Wn)          // 4096
#define BHW  (Bn*HW)          // 16384
#define EPSV 1e-5f

// ---------------- scratch (device globals: no allocation allowed) ----------
__device__ __align__(16) float g_k[BHW*CPn];     // key map  (pixel-major)
__device__ __align__(16) float g_q[BHW*CPn];     // query map
__device__ __align__(16) float g_x[BHW*CPn];     // value map
__device__ __align__(16) float g_s[81*BHW];      // scores -> combined weights
__device__ __align__(16) float g_pre[BHW*CPn];   // attention output
__device__ __align__(16) float g_y[Bn*Cn*HW];    // conv-f output (channel-major)
__device__ float g_sum[Cn], g_sqs[Cn], g_mean[Cn], g_inv[Cn];

// ---------------- kernel 0: zero the stat accumulators ---------------------
__global__ void zero_stats_kernel() {
    int i = threadIdx.x;
    if (i < Cn) { g_sum[i] = 0.f; g_sqs[i] = 0.f; }
}

// ---------------- kernel 1: km/qm/xm 1x1 convs (256 -> 32), pixel-major ----
__global__ __launch_bounds__(256) void qkx_kernel(
    const float* __restrict__ x,  const float* __restrict__ vessel,
    const float* __restrict__ wk, const float* __restrict__ bk,
    const float* __restrict__ wq, const float* __restrict__ bq,
    const float* __restrict__ wx, const float* __restrict__ bx)
{
    __shared__ float ws[Cn*CPn];          // transposed: ws[c*32+o]
    const int map = blockIdx.y;
    const float* __restrict__ w    = (map == 0) ? wk : (map == 1) ? wq : wx;
    const float* __restrict__ bias = (map == 0) ? bk : (map == 1) ? bq : bx;
    float* __restrict__ out        = (map == 0) ? g_k : (map == 1) ? g_q : g_x;

    const int tid = threadIdx.x;
    for (int i = tid; i < Cn*CPn; i += 256) {      // coalesced read of w[o][c]
        int o = i >> 8, c = i & 255;
        ws[c*CPn + o] = w[i];
    }
    __syncthreads();

    const int p  = blockIdx.x * 256 + tid;         // global pixel
    const int b  = p >> 12, hw = p & 4095;
    const float* __restrict__ xp = x + (size_t)b*Cn*HW + hw;

    float acc[CPn];
#pragma unroll
    for (int o = 0; o < CPn; ++o) acc[o] = 0.f;

    for (int c = 0; c < Cn; ++c) {
        float xv = __ldg(xp + c*HW);
        const float4* w4 = (const float4*)(ws + c*CPn);
#pragma unroll
        for (int j = 0; j < 8; ++j) {
            float4 wv = w4[j];
            acc[4*j+0] += wv.x*xv; acc[4*j+1] += wv.y*xv;
            acc[4*j+2] += wv.z*xv; acc[4*j+3] += wv.w*xv;
        }
    }

    const float scale = (map == 0) ? vessel[p] : 1.f;
    float4* op = (float4*)(out + (size_t)p*CPn);
#pragma unroll
    for (int j = 0; j < 8; ++j) {
        float4 v;
        v.x = (acc[4*j+0] + bias[4*j+0]) * scale;
        v.y = (acc[4*j+1] + bias[4*j+1]) * scale;
        v.z = (acc[4*j+2] + bias[4*j+2]) * scale;
        v.w = (acc[4*j+3] + bias[4*j+3]) * scale;
        op[j] = v;
    }
}

// ---------------- kernel 2a: scores -----------------------------------------
// thread = (pixel, dy). Computes 9 scores (dx = -4..4). OOB -> exact 0.
// Layout: g_s[off][p], off = dyi*9 + dxi.
__global__ __launch_bounds__(256) void score_kernel()
{
    const int dyi = blockIdx.y;                    // 0..8
    const int p   = blockIdx.x * 256 + threadIdx.x;
    const int b   = p >> 12, hw = p & 4095;
    const int y   = hw >> 6, x = hw & 63;
    const int yy  = y + dyi - 4;
    const bool yok = (unsigned)yy < (unsigned)Hn;

    // query in registers (32 floats)
    const float4* qp = (const float4*)(g_q + (size_t)p*CPn);
    float4 q[8];
#pragma unroll
    for (int j = 0; j < 8; ++j) q[j] = qp[j];

    const float* __restrict__ krow = g_k + ((size_t)b*HW + (size_t)yy*Wn)*CPn;

#pragma unroll
    for (int dxi = 0; dxi < 9; ++dxi) {
        int xx = x + dxi - 4;
        float s = 0.f;
        if (yok && (unsigned)xx < (unsigned)Wn) {
            const float4* kp = (const float4*)(krow + (size_t)xx*CPn);
#pragma unroll
            for (int j = 0; j < 8; ++j) {
                float4 kv = kp[j];
                s += kv.x*q[j].x + kv.y*q[j].y + kv.z*q[j].z + kv.w*q[j].w;
            }
        }
        g_s[(size_t)(dyi*9 + dxi)*BHW + p] = s;
    }
}

// ---------------- kernel 2b: nested-window softmax -> combined weights -----
__global__ __launch_bounds__(256) void softmax_kernel()
{
    const int p = blockIdx.x * 256 + threadIdx.x;

    float s[81];
#pragma unroll
    for (int i = 0; i < 81; ++i) s[i] = g_s[(size_t)i*BHW + p];

    float m = s[0];
#pragma unroll
    for (int i = 1; i < 81; ++i) m = fmaxf(m, s[i]);

    float S9 = 0.f, S7 = 0.f, S5 = 0.f, S3 = 0.f;
#pragma unroll
    for (int iy = 0; iy < 9; ++iy) {
#pragma unroll
        for (int ix = 0; ix < 9; ++ix) {
            int i = iy*9 + ix;
            float ev = __expf(s[i] - m);
            s[i] = ev;
            S9 += ev;
            if (iy >= 1 && iy <= 7 && ix >= 1 && ix <= 7) S7 += ev;
            if (iy >= 2 && iy <= 6 && ix >= 2 && ix <= 6) S5 += ev;
            if (iy >= 3 && iy <= 5 && ix >= 3 && ix <= 5) S3 += ev;
        }
    }
    const float r9 = 1.f/S9, r7 = 1.f/S7, r5 = 1.f/S5, r3 = 1.f/S3;
#pragma unroll
    for (int iy = 0; iy < 9; ++iy) {
#pragma unroll
        for (int ix = 0; ix < 9; ++ix) {
            int i = iy*9 + ix;
            float cf = r9;
            if (iy >= 1 && iy <= 7 && ix >= 1 && ix <= 7) cf += r7;
            if (iy >= 2 && iy <= 6 && ix >= 2 && ix <= 6) cf += r5;
            if (iy >= 3 && iy <= 5 && ix >= 3 && ix <= 5) cf += r3;
            g_s[(size_t)i*BHW + p] = s[i] * cf;
        }
    }
}

// ---------------- kernel 2c: apply weights ----------------------------------
// thread = (pixel, 8-channel group). Block = 64 pixels (one image row) x 4 grp.
__global__ __launch_bounds__(256) void apply_kernel()
{
    const int tid = threadIdx.x;
    const int g   = tid & 3;                  // channel group (8 ch)
    const int p   = blockIdx.x * 64 + (tid >> 2);
    const int b   = p >> 12, hw = p & 4095;
    const int y   = hw >> 6, x = hw & 63;

    const float* __restrict__ xb = g_x + (size_t)b*HW*CPn + g*8;

    float acc[8];
#pragma unroll
    for (int j = 0; j < 8; ++j) acc[j] = 0.f;

#pragma unroll
    for (int dyi = 0; dyi < 9; ++dyi) {
        int yy = y + dyi - 4;
        bool yok = (unsigned)yy < (unsigned)Hn;
        const float* rowp = xb + (ptrdiff_t)(yy*Wn)*CPn;
        const float* wrow = g_s + (size_t)(dyi*9)*BHW + p;
#pragma unroll
        for (int dxi = 0; dxi < 9; ++dxi) {
            int xx = x + dxi - 4;
            if (yok && (unsigned)xx < (unsigned)Wn) {
                float wgt = wrow[(size_t)dxi*BHW];
                const float4* xp = (const float4*)(rowp + (size_t)xx*CPn);
                float4 a = xp[0], b4 = xp[1];
                acc[0] += wgt*a.x;  acc[1] += wgt*a.y;
                acc[2] += wgt*a.z;  acc[3] += wgt*a.w;
                acc[4] += wgt*b4.x; acc[5] += wgt*b4.y;
                acc[6] += wgt*b4.z; acc[7] += wgt*b4.w;
            }
        }
    }
    float4* op = (float4*)(g_pre + (size_t)p*CPn + g*8);
    op[0] = make_float4(acc[0], acc[1], acc[2], acc[3]);
    op[1] = make_float4(acc[4], acc[5], acc[6], acc[7]);
}

// ---------------- kernel 3: conv-f (32->256) + BN partial stats ------------
// VERIFIED round-1 version: thread = output channel, block = 32 pixels.
__global__ __launch_bounds__(256) void convf_kernel(
    const float* __restrict__ wf, const float* __restrict__ bf)
{
    __shared__ float pre_s[32*CPn];
    __shared__ float y_s[32*257];

    const int tid = threadIdx.x;       // = output channel
    const int p0  = blockIdx.x * 32;   // global pixel base

    float wfr[CPn];
    const float4* wp = (const float4*)(wf + tid*CPn);
#pragma unroll
    for (int j = 0; j < 8; ++j) {
        float4 v = wp[j];
        wfr[4*j+0] = v.x; wfr[4*j+1] = v.y; wfr[4*j+2] = v.z; wfr[4*j+3] = v.w;
    }
    for (int i = tid; i < 32*CPn; i += 256)
        pre_s[i] = g_pre[(size_t)p0*CPn + i];
    __syncthreads();

    const float bfv = bf[tid];
    float sum = 0.f, sq = 0.f;
#pragma unroll 1
    for (int pl = 0; pl < 32; ++pl) {
        const float4* pp = (const float4*)(pre_s + pl*CPn);
        float v = bfv;
#pragma unroll
        for (int j = 0; j < 8; ++j) {
            float4 pv = pp[j];
            v += wfr[4*j+0]*pv.x + wfr[4*j+1]*pv.y
               + wfr[4*j+2]*pv.z + wfr[4*j+3]*pv.w;
        }
        sum += v; sq += v*v;
        y_s[pl*257 + tid] = v;
    }
    atomicAdd(&g_sum[tid], sum);
    atomicAdd(&g_sqs[tid], sq);
    __syncthreads();

    const int b = p0 >> 12, hw0 = p0 & 4095;
    for (int i = tid; i < 32*Cn; i += 256) {
        int c = i >> 5, pl = i & 31;        // lanes sweep pl -> coalesced STG
        g_y[((size_t)(b*Cn + c))*HW + hw0 + pl] = y_s[pl*257 + c];
    }
}

// ---------------- kernel 4: finalize BN stats ------------------------------
__global__ void finalize_stats_kernel() {
    int c = threadIdx.x;
    if (c < Cn) {
        const float invn = 1.f / (float)BHW;
        float mean = g_sum[c] * invn;
        float var  = g_sqs[c] * invn - mean*mean;
        g_mean[c] = mean;
        g_inv[c]  = rsqrtf(var + EPSV);
    }
}

// ---------------- kernel 5: residual + affine (elementwise) ----------------
__global__ __launch_bounds__(256) void out_kernel(
    const float* __restrict__ x, const float* __restrict__ gamma,
    const float* __restrict__ beta, float* __restrict__ out)
{
    int idx = blockIdx.x * 256 + threadIdx.x;   // 4,194,304 total
    int c = (idx >> 12) & 255;
    float yv = g_y[idx];
    out[idx] = x[idx] + gamma[c] * ((yv - g_mean[c]) * g_inv[c]) + beta[c];
}

// ---------------------------------------------------------------------------
extern "C" void kernel_launch(void* const* d_in, const int* in_sizes, int n_in,
                              void* d_out, int out_size)
{
    const float* x      = (const float*)d_in[0];
    const float* vessel = (const float*)d_in[1];
    const float* wk     = (const float*)d_in[2];
    const float* bk     = (const float*)d_in[3];
    const float* wq     = (const float*)d_in[4];
    const float* bq     = (const float*)d_in[5];
    const float* wx     = (const float*)d_in[6];
    const float* bx     = (const float*)d_in[7];
    const float* wf     = (const float*)d_in[8];
    const float* bf     = (const float*)d_in[9];
    const float* gamma  = (const float*)d_in[10];
    const float* beta   = (const float*)d_in[11];
    float* out          = (float*)d_out;

    zero_stats_kernel<<<1, 256>>>();
    qkx_kernel<<<dim3(BHW/256, 3), 256>>>(x, vessel, wk, bk, wq, bq, wx, bx);
    score_kernel<<<dim3(BHW/256, 9), 256>>>();
    softmax_kernel<<<BHW/256, 256>>>();
    apply_kernel<<<BHW*4/256, 256>>>();
    convf_kernel<<<BHW/32, 256>>>(wf, bf);
    finalize_stats_kernel<<<1, 256>>>();
    out_kernel<<<Bn*Cn*HW/256, 256>>>(x, gamma, beta, out);
}

// round 9
// speedup vs baseline: 1.7850x; 1.0419x over previous
#include <cuda_runtime.h>

#define Bn   4
#define Cn   256
#define CPn  32
#define Hn   64
#define Wn   64
#define HW   (Hn*Wn)          // 4096
#define BHW  (Bn*HW)          // 16384
#define EPSV 1e-5f

// ---------------- scratch (device globals: no allocation allowed) ----------
__device__ __align__(16) float g_k[BHW*CPn];     // key map  (pixel-major)
__device__ __align__(16) float g_q[BHW*CPn];     // query map
__device__ __align__(16) float g_x[BHW*CPn];     // value map
__device__ __align__(16) float g_s[81*BHW];      // scores -> combined weights
__device__ __align__(16) float g_pre[BHW*CPn];   // attention output
__device__ __align__(16) float g_y[Bn*Cn*HW];    // conv-f output (channel-major)
__device__ float g_mean[Cn], g_inv[Cn];

// ---------------- packed f32x2 helpers (FFMA2: PTX-only pattern) -----------
__device__ __forceinline__ unsigned long long pk2(float lo, float hi) {
    unsigned long long r;
    asm("mov.b64 %0, {%1, %2};" : "=l"(r) : "f"(lo), "f"(hi));
    return r;
}
__device__ __forceinline__ void fma2(unsigned long long& d,
                                     unsigned long long a, unsigned long long b) {
    asm("fma.rn.f32x2 %0, %1, %2, %0;" : "+l"(d) : "l"(a), "l"(b));
}
__device__ __forceinline__ void upk2(unsigned long long v, float& lo, float& hi) {
    asm("mov.b64 {%0, %1}, %2;" : "=f"(lo), "=f"(hi) : "l"(v));
}

// ---------------- kernel 1: km/qm/xm 1x1 convs (256 -> 32), pixel-major ----
__global__ __launch_bounds__(256) void qkx_kernel(
    const float* __restrict__ x,  const float* __restrict__ vessel,
    const float* __restrict__ wk, const float* __restrict__ bk,
    const float* __restrict__ wq, const float* __restrict__ bq,
    const float* __restrict__ wx, const float* __restrict__ bx)
{
    __shared__ float ws[Cn*CPn];          // transposed: ws[c*32+o]
    const int map = blockIdx.y;
    const float* __restrict__ w    = (map == 0) ? wk : (map == 1) ? wq : wx;
    const float* __restrict__ bias = (map == 0) ? bk : (map == 1) ? bq : bx;
    float* __restrict__ out        = (map == 0) ? g_k : (map == 1) ? g_q : g_x;

    const int tid = threadIdx.x;
    for (int i = tid; i < Cn*CPn; i += 256) {      // coalesced read of w[o][c]
        int o = i >> 8, c = i & 255;
        ws[c*CPn + o] = w[i];
    }
    __syncthreads();

    const int p  = blockIdx.x * 256 + tid;         // global pixel
    const int b  = p >> 12, hw = p & 4095;
    const float* __restrict__ xp = x + (size_t)b*Cn*HW + hw;

    unsigned long long acc2[16];
#pragma unroll
    for (int j = 0; j < 16; ++j) acc2[j] = 0ULL;

    for (int c = 0; c < Cn; ++c) {
        float xv = __ldg(xp + c*HW);
        unsigned long long xv2 = pk2(xv, xv);
        // lane-uniform broadcast reads; c*CPn floats = 128B-aligned -> 8B ok
        const unsigned long long* w2 = (const unsigned long long*)(ws + c*CPn);
#pragma unroll
        for (int j = 0; j < 16; ++j) fma2(acc2[j], w2[j], xv2);
    }

    const float scale = (map == 0) ? vessel[p] : 1.f;
    float4* op = (float4*)(out + (size_t)p*CPn);
#pragma unroll
    for (int j = 0; j < 8; ++j) {
        float a0, a1, a2, a3;
        upk2(acc2[2*j],   a0, a1);
        upk2(acc2[2*j+1], a2, a3);
        float4 v;
        v.x = (a0 + bias[4*j+0]) * scale;
        v.y = (a1 + bias[4*j+1]) * scale;
        v.z = (a2 + bias[4*j+2]) * scale;
        v.w = (a3 + bias[4*j+3]) * scale;
        op[j] = v;
    }
}

// ---------------- kernel 2a: scores -----------------------------------------
// thread = (pixel, dy). Computes 9 scores (dx = -4..4). OOB -> exact 0.
__global__ __launch_bounds__(256) void score_kernel()
{
    const int dyi = blockIdx.y;                    // 0..8
    const int p   = blockIdx.x * 256 + threadIdx.x;
    const int b   = p >> 12, hw = p & 4095;
    const int y   = hw >> 6, x = hw & 63;
    const int yy  = y + dyi - 4;
    const bool yok = (unsigned)yy < (unsigned)Hn;

    const float4* qp = (const float4*)(g_q + (size_t)p*CPn);
    float4 q[8];
#pragma unroll
    for (int j = 0; j < 8; ++j) q[j] = qp[j];

    const float* __restrict__ krow = g_k + ((size_t)b*HW + (size_t)yy*Wn)*CPn;

#pragma unroll
    for (int dxi = 0; dxi < 9; ++dxi) {
        int xx = x + dxi - 4;
        float s = 0.f;
        if (yok && (unsigned)xx < (unsigned)Wn) {
            const float4* kp = (const float4*)(krow + (size_t)xx*CPn);
#pragma unroll
            for (int j = 0; j < 8; ++j) {
                float4 kv = kp[j];
                s += kv.x*q[j].x + kv.y*q[j].y + kv.z*q[j].z + kv.w*q[j].w;
            }
        }
        g_s[(size_t)(dyi*9 + dxi)*BHW + p] = s;
    }
}

// ---------------- kernel 2b: nested-window softmax -> combined weights -----
// 64-thread blocks -> 256 blocks (was 64: SM starvation at 128 regs).
__global__ __launch_bounds__(64) void softmax_kernel()
{
    const int p = blockIdx.x * 64 + threadIdx.x;

    float s[81];
#pragma unroll
    for (int i = 0; i < 81; ++i) s[i] = g_s[(size_t)i*BHW + p];

    float m = s[0];
#pragma unroll
    for (int i = 1; i < 81; ++i) m = fmaxf(m, s[i]);

    float S9 = 0.f, S7 = 0.f, S5 = 0.f, S3 = 0.f;
#pragma unroll
    for (int iy = 0; iy < 9; ++iy) {
#pragma unroll
        for (int ix = 0; ix < 9; ++ix) {
            int i = iy*9 + ix;
            float ev = __expf(s[i] - m);
            s[i] = ev;
            S9 += ev;
            if (iy >= 1 && iy <= 7 && ix >= 1 && ix <= 7) S7 += ev;
            if (iy >= 2 && iy <= 6 && ix >= 2 && ix <= 6) S5 += ev;
            if (iy >= 3 && iy <= 5 && ix >= 3 && ix <= 5) S3 += ev;
        }
    }
    const float r9 = 1.f/S9, r7 = 1.f/S7, r5 = 1.f/S5, r3 = 1.f/S3;
#pragma unroll
    for (int iy = 0; iy < 9; ++iy) {
#pragma unroll
        for (int ix = 0; ix < 9; ++ix) {
            int i = iy*9 + ix;
            float cf = r9;
            if (iy >= 1 && iy <= 7 && ix >= 1 && ix <= 7) cf += r7;
            if (iy >= 2 && iy <= 6 && ix >= 2 && ix <= 6) cf += r5;
            if (iy >= 3 && iy <= 5 && ix >= 3 && ix <= 5) cf += r3;
            g_s[(size_t)i*BHW + p] = s[i] * cf;
        }
    }
}

// ---------------- kernel 2c: apply weights ----------------------------------
__global__ __launch_bounds__(256) void apply_kernel()
{
    const int tid = threadIdx.x;
    const int g   = tid & 3;                  // channel group (8 ch)
    const int p   = blockIdx.x * 64 + (tid >> 2);
    const int b   = p >> 12, hw = p & 4095;
    const int y   = hw >> 6, x = hw & 63;

    const float* __restrict__ xb = g_x + (size_t)b*HW*CPn + g*8;

    float acc[8];
#pragma unroll
    for (int j = 0; j < 8; ++j) acc[j] = 0.f;

#pragma unroll
    for (int dyi = 0; dyi < 9; ++dyi) {
        int yy = y + dyi - 4;
        bool yok = (unsigned)yy < (unsigned)Hn;
        const float* rowp = xb + (ptrdiff_t)(yy*Wn)*CPn;
        const float* wrow = g_s + (size_t)(dyi*9)*BHW + p;
#pragma unroll
        for (int dxi = 0; dxi < 9; ++dxi) {
            int xx = x + dxi - 4;
            if (yok && (unsigned)xx < (unsigned)Wn) {
                float wgt = wrow[(size_t)dxi*BHW];
                const float4* xp = (const float4*)(rowp + (size_t)xx*CPn);
                float4 a = xp[0], b4 = xp[1];
                acc[0] += wgt*a.x;  acc[1] += wgt*a.y;
                acc[2] += wgt*a.z;  acc[3] += wgt*a.w;
                acc[4] += wgt*b4.x; acc[5] += wgt*b4.y;
                acc[6] += wgt*b4.z; acc[7] += wgt*b4.w;
            }
        }
    }
    float4* op = (float4*)(g_pre + (size_t)p*CPn + g*8);
    op[0] = make_float4(acc[0], acc[1], acc[2], acc[3]);
    op[1] = make_float4(acc[4], acc[5], acc[6], acc[7]);
}

// ---------------- kernel 3: conv-f (32->256), no stats ---------------------
// Block = 32 pixels. tid -> (pl = tid&31 pixel lane, g = tid>>5 group of 32 ch).
// Each thread computes channels c = g*32..g*32+31 for its pixel: 8*32 = 256. ✓
__global__ __launch_bounds__(256) void convf_kernel(
    const float* __restrict__ wf, const float* __restrict__ bf)
{
    __shared__ float wf_s[Cn*CPn];      // 32 KB, [c][k]
    __shared__ float pre_s[32*33];      // pitch-33: conflict-free

    const int tid = threadIdx.x;
    const int pl  = tid & 31;
    const int g   = tid >> 5;           // 0..7
    const int p0  = blockIdx.x * 32;
    const int b   = p0 >> 12;
    const int hw  = (p0 & 4095) + pl;

    for (int i = tid; i < Cn*CPn; i += 256) wf_s[i] = wf[i];
    for (int i = tid; i < 32*CPn; i += 256) {
        int pli = i >> 5, j = i & 31;
        pre_s[pli*33 + j] = g_pre[(size_t)(p0 + pli)*CPn + j];
    }
    __syncthreads();

    // own pixel's 32 pre values, packed into 16 f32x2 regs
    unsigned long long pv2[16];
#pragma unroll
    for (int j = 0; j < 16; ++j)
        pv2[j] = pk2(pre_s[pl*33 + 2*j], pre_s[pl*33 + 2*j + 1]);

#pragma unroll 1
    for (int j = 0; j < 32; ++j) {
        const int c = g*32 + j;
        // lane-uniform broadcast; c*CPn floats = 128B-aligned -> 8B ok
        const unsigned long long* w2 = (const unsigned long long*)(wf_s + c*CPn);
        unsigned long long a2 = 0ULL;
#pragma unroll
        for (int q4 = 0; q4 < 16; ++q4) fma2(a2, w2[q4], pv2[q4]);
        float lo, hi; upk2(a2, lo, hi);
        g_y[((size_t)(b*Cn + c))*HW + hw] = bf[c] + lo + hi;  // coalesced per warp
    }
}

// ---------------- kernel 4: BN stats (one block per channel, no atomics) ---
__global__ __launch_bounds__(256) void stats_kernel()
{
    __shared__ float sm_s[8], sm_q[8];
    const int c   = blockIdx.x;
    const int tid = threadIdx.x;

    float sum = 0.f, sq = 0.f;
#pragma unroll
    for (int b = 0; b < Bn; ++b) {
        const float* __restrict__ yp = g_y + ((size_t)(b*Cn + c))*HW;
        for (int i = tid; i < HW; i += 256) {
            float v = yp[i];
            sum += v; sq += v*v;
        }
    }
#pragma unroll
    for (int off = 16; off; off >>= 1) {
        sum += __shfl_xor_sync(0xFFFFFFFFu, sum, off);
        sq  += __shfl_xor_sync(0xFFFFFFFFu, sq,  off);
    }
    if ((tid & 31) == 0) { sm_s[tid >> 5] = sum; sm_q[tid >> 5] = sq; }
    __syncthreads();
    if (tid == 0) {
        float s = 0.f, q = 0.f;
#pragma unroll
        for (int w = 0; w < 8; ++w) { s += sm_s[w]; q += sm_q[w]; }
        const float invn = 1.f / (float)BHW;
        float mean = s * invn;
        float var  = q * invn - mean*mean;
        g_mean[c] = mean;
        g_inv[c]  = rsqrtf(var + EPSV);
    }
}

// ---------------- kernel 5: residual + affine (elementwise) ----------------
__global__ __launch_bounds__(256) void out_kernel(
    const float* __restrict__ x, const float* __restrict__ gamma,
    const float* __restrict__ beta, float* __restrict__ out)
{
    int idx = blockIdx.x * 256 + threadIdx.x;   // 4,194,304 total
    int c = (idx >> 12) & 255;
    float yv = g_y[idx];
    out[idx] = x[idx] + gamma[c] * ((yv - g_mean[c]) * g_inv[c]) + beta[c];
}

// ---------------------------------------------------------------------------
extern "C" void kernel_launch(void* const* d_in, const int* in_sizes, int n_in,
                              void* d_out, int out_size)
{
    const float* x      = (const float*)d_in[0];
    const float* vessel = (const float*)d_in[1];
    const float* wk     = (const float*)d_in[2];
    const float* bk     = (const float*)d_in[3];
    const float* wq     = (const float*)d_in[4];
    const float* bq     = (const float*)d_in[5];
    const float* wx     = (const float*)d_in[6];
    const float* bx     = (const float*)d_in[7];
    const float* wf     = (const float*)d_in[8];
    const float* bf     = (const float*)d_in[9];
    const float* gamma  = (const float*)d_in[10];
    const float* beta   = (const float*)d_in[11];
    float* out          = (float*)d_out;

    qkx_kernel<<<dim3(BHW/256, 3), 256>>>(x, vessel, wk, bk, wq, bq, wx, bx);
    score_kernel<<<dim3(BHW/256, 9), 256>>>();
    softmax_kernel<<<BHW/64, 64>>>();
    apply_kernel<<<BHW*4/256, 256>>>();
    convf_kernel<<<BHW/32, 256>>>(wf, bf);
    stats_kernel<<<Cn, 256>>>();
    out_kernel<<<Bn*Cn*HW/256, 256>>>(x, gamma, beta, out);
}

// round 11
// speedup vs baseline: 1.8579x; 1.0408x over previous
#include <cuda_runtime.h>

#define Bn   4
#define Cn   256
#define CPn  32
#define Hn   64
#define Wn   64
#define HW   (Hn*Wn)          // 4096
#define BHW  (Bn*HW)          // 16384
#define EPSV 1e-5f

// ---------------- scratch (device globals: no allocation allowed) ----------
__device__ __align__(16) float g_k[BHW*CPn];     // key map  (pixel-major)
__device__ __align__(16) float g_q[BHW*CPn];     // query map
__device__ __align__(16) float g_x[BHW*CPn];     // value map
__device__ __align__(16) float g_s[81*BHW];      // scores -> combined weights
__device__ __align__(16) float g_pre[BHW*CPn];   // attention output
__device__ __align__(16) float g_y[Bn*Cn*HW];    // conv-f output (channel-major)
__device__ float g_mean[Cn], g_inv[Cn];

// ---------------- packed f32x2 helpers (FFMA2: PTX-only pattern) -----------
__device__ __forceinline__ unsigned long long pk2(float lo, float hi) {
    unsigned long long r;
    asm("mov.b64 %0, {%1, %2};" : "=l"(r) : "f"(lo), "f"(hi));
    return r;
}
__device__ __forceinline__ void fma2(unsigned long long& d,
                                     unsigned long long a, unsigned long long b) {
    asm("fma.rn.f32x2 %0, %1, %2, %0;" : "+l"(d) : "l"(a), "l"(b));
}
__device__ __forceinline__ void upk2(unsigned long long v, float& lo, float& hi) {
    asm("mov.b64 {%0, %1}, %2;" : "=f"(lo), "=f"(hi) : "l"(v));
}

// ---------------- kernel 1: km/qm/xm 1x1 convs (256 -> 32), pixel-major ----
__global__ __launch_bounds__(256) void qkx_kernel(
    const float* __restrict__ x,  const float* __restrict__ vessel,
    const float* __restrict__ wk, const float* __restrict__ bk,
    const float* __restrict__ wq, const float* __restrict__ bq,
    const float* __restrict__ wx, const float* __restrict__ bx)
{
    __shared__ float ws[Cn*CPn];          // transposed: ws[c*32+o]
    const int map = blockIdx.y;
    const float* __restrict__ w    = (map == 0) ? wk : (map == 1) ? wq : wx;
    const float* __restrict__ bias = (map == 0) ? bk : (map == 1) ? bq : bx;
    float* __restrict__ out        = (map == 0) ? g_k : (map == 1) ? g_q : g_x;

    const int tid = threadIdx.x;
    for (int i = tid; i < Cn*CPn; i += 256) {      // coalesced read of w[o][c]
        int o = i >> 8, c = i & 255;
        ws[c*CPn + o] = w[i];
    }
    __syncthreads();

    const int p  = blockIdx.x * 256 + tid;         // global pixel
    const int b  = p >> 12, hw = p & 4095;
    const float* __restrict__ xp = x + (size_t)b*Cn*HW + hw;

    unsigned long long acc2[16];
#pragma unroll
    for (int j = 0; j < 16; ++j) acc2[j] = 0ULL;

#pragma unroll 8
    for (int c = 0; c < Cn; ++c) {
        float xv = __ldg(xp + c*HW);
        unsigned long long xv2 = pk2(xv, xv);
        const unsigned long long* w2 = (const unsigned long long*)(ws + c*CPn);
#pragma unroll
        for (int j = 0; j < 16; ++j) fma2(acc2[j], w2[j], xv2);
    }

    const float scale = (map == 0) ? vessel[p] : 1.f;
    float4* op = (float4*)(out + (size_t)p*CPn);
#pragma unroll
    for (int j = 0; j < 8; ++j) {
        float a0, a1, a2, a3;
        upk2(acc2[2*j],   a0, a1);
        upk2(acc2[2*j+1], a2, a3);
        float4 v;
        v.x = (a0 + bias[4*j+0]) * scale;
        v.y = (a1 + bias[4*j+1]) * scale;
        v.z = (a2 + bias[4*j+2]) * scale;
        v.w = (a3 + bias[4*j+3]) * scale;
        op[j] = v;
    }
}

// ---------------- kernel 2a: scores -----------------------------------------
// thread = (pixel, dy). Computes 9 scores (dx = -4..4). OOB -> exact 0.
__global__ __launch_bounds__(256) void score_kernel()
{
    const int dyi = blockIdx.y;                    // 0..8
    const int p   = blockIdx.x * 256 + threadIdx.x;
    const int b   = p >> 12, hw = p & 4095;
    const int y   = hw >> 6, x = hw & 63;
    const int yy  = y + dyi - 4;
    const bool yok = (unsigned)yy < (unsigned)Hn;

    const float4* qp = (const float4*)(g_q + (size_t)p*CPn);
    float4 q[8];
#pragma unroll
    for (int j = 0; j < 8; ++j) q[j] = qp[j];

    const float* __restrict__ krow = g_k + ((size_t)b*HW + (size_t)yy*Wn)*CPn;

#pragma unroll
    for (int dxi = 0; dxi < 9; ++dxi) {
        int xx = x + dxi - 4;
        float s = 0.f;
        if (yok && (unsigned)xx < (unsigned)Wn) {
            const float4* kp = (const float4*)(krow + (size_t)xx*CPn);
#pragma unroll
            for (int j = 0; j < 8; ++j) {
                float4 kv = kp[j];
                s += kv.x*q[j].x + kv.y*q[j].y + kv.z*q[j].z + kv.w*q[j].w;
            }
        }
        g_s[(size_t)(dyi*9 + dxi)*BHW + p] = s;
    }
}

// ---------------- kernel 2b: nested-window softmax -> combined weights -----
__global__ __launch_bounds__(64) void softmax_kernel()
{
    const int p = blockIdx.x * 64 + threadIdx.x;

    float s[81];
#pragma unroll
    for (int i = 0; i < 81; ++i) s[i] = g_s[(size_t)i*BHW + p];

    float m = s[0];
#pragma unroll
    for (int i = 1; i < 81; ++i) m = fmaxf(m, s[i]);

    float S9 = 0.f, S7 = 0.f, S5 = 0.f, S3 = 0.f;
#pragma unroll
    for (int iy = 0; iy < 9; ++iy) {
#pragma unroll
        for (int ix = 0; ix < 9; ++ix) {
            int i = iy*9 + ix;
            float ev = __expf(s[i] - m);
            s[i] = ev;
            S9 += ev;
            if (iy >= 1 && iy <= 7 && ix >= 1 && ix <= 7) S7 += ev;
            if (iy >= 2 && iy <= 6 && ix >= 2 && ix <= 6) S5 += ev;
            if (iy >= 3 && iy <= 5 && ix >= 3 && ix <= 5) S3 += ev;
        }
    }
    const float r9 = 1.f/S9, r7 = 1.f/S7, r5 = 1.f/S5, r3 = 1.f/S3;
#pragma unroll
    for (int iy = 0; iy < 9; ++iy) {
#pragma unroll
        for (int ix = 0; ix < 9; ++ix) {
            int i = iy*9 + ix;
            float cf = r9;
            if (iy >= 1 && iy <= 7 && ix >= 1 && ix <= 7) cf += r7;
            if (iy >= 2 && iy <= 6 && ix >= 2 && ix <= 6) cf += r5;
            if (iy >= 3 && iy <= 5 && ix >= 3 && ix <= 5) cf += r3;
            g_s[(size_t)i*BHW + p] = s[i] * cf;
        }
    }
}

// ---------------- kernel 2c: apply weights ----------------------------------
// thread = (pixel, group of 4 channels). 32 px x 8 groups per block,
// grid = 512 blocks (2x round-9) -> 4096 warps, regs ~40.
__global__ __launch_bounds__(256) void apply_kernel()
{
    const int tid = threadIdx.x;
    const int g   = tid & 7;                  // channel group (4 ch)
    const int p   = blockIdx.x * 32 + (tid >> 3);
    const int b   = p >> 12, hw = p & 4095;
    const int y   = hw >> 6, x = hw & 63;

    const float* __restrict__ xb = g_x + (size_t)b*HW*CPn + g*4;

    float acc0 = 0.f, acc1 = 0.f, acc2 = 0.f, acc3 = 0.f;

#pragma unroll
    for (int dyi = 0; dyi < 9; ++dyi) {
        int yy = y + dyi - 4;
        bool yok = (unsigned)yy < (unsigned)Hn;
        const float* rowp = xb + (ptrdiff_t)(yy*Wn)*CPn;
        const float* wrow = g_s + (size_t)(dyi*9)*BHW + p;
#pragma unroll
        for (int dxi = 0; dxi < 9; ++dxi) {
            int xx = x + dxi - 4;
            if (yok && (unsigned)xx < (unsigned)Wn) {
                float wgt = wrow[(size_t)dxi*BHW];
                float4 a = *(const float4*)(rowp + (size_t)xx*CPn);
                acc0 += wgt*a.x; acc1 += wgt*a.y;
                acc2 += wgt*a.z; acc3 += wgt*a.w;
            }
        }
    }
    *(float4*)(g_pre + (size_t)p*CPn + g*4) = make_float4(acc0, acc1, acc2, acc3);
}

// ---------------- kernel 3: conv-f (32->256), no stats ---------------------
__global__ __launch_bounds__(256) void convf_kernel(
    const float* __restrict__ wf, const float* __restrict__ bf)
{
    __shared__ float wf_s[Cn*CPn];      // 32 KB, [c][k]
    __shared__ float pre_s[32*33];      // pitch-33: conflict-free

    const int tid = threadIdx.x;
    const int pl  = tid & 31;
    const int g   = tid >> 5;           // 0..7
    const int p0  = blockIdx.x * 32;
    const int b   = p0 >> 12;
    const int hw  = (p0 & 4095) + pl;

    for (int i = tid; i < Cn*CPn; i += 256) wf_s[i] = wf[i];
    for (int i = tid; i < 32*CPn; i += 256) {
        int pli = i >> 5, j = i & 31;
        pre_s[pli*33 + j] = g_pre[(size_t)(p0 + pli)*CPn + j];
    }
    __syncthreads();

    unsigned long long pv2[16];
#pragma unroll
    for (int j = 0; j < 16; ++j)
        pv2[j] = pk2(pre_s[pl*33 + 2*j], pre_s[pl*33 + 2*j + 1]);

#pragma unroll 1
    for (int j = 0; j < 32; ++j) {
        const int c = g*32 + j;
        const unsigned long long* w2 = (const unsigned long long*)(wf_s + c*CPn);
        unsigned long long a2 = 0ULL;
#pragma unroll
        for (int q4 = 0; q4 < 16; ++q4) fma2(a2, w2[q4], pv2[q4]);
        float lo, hi; upk2(a2, lo, hi);
        g_y[((size_t)(b*Cn + c))*HW + hw] = bf[c] + lo + hi;  // coalesced per warp
    }
}

// ---------------- kernel 4: BN stats (one block per channel, no atomics) ---
__global__ __launch_bounds__(256) void stats_kernel()
{
    __shared__ float sm_s[8], sm_q[8];
    const int c   = blockIdx.x;
    const int tid = threadIdx.x;

    float sum = 0.f, sq = 0.f;
#pragma unroll
    for (int b = 0; b < Bn; ++b) {
        const float* __restrict__ yp = g_y + ((size_t)(b*Cn + c))*HW;
        for (int i = tid; i < HW; i += 256) {
            float v = yp[i];
            sum += v; sq += v*v;
        }
    }
#pragma unroll
    for (int off = 16; off; off >>= 1) {
        sum += __shfl_xor_sync(0xFFFFFFFFu, sum, off);
        sq  += __shfl_xor_sync(0xFFFFFFFFu, sq,  off);
    }
    if ((tid & 31) == 0) { sm_s[tid >> 5] = sum; sm_q[tid >> 5] = sq; }
    __syncthreads();
    if (tid == 0) {
        float s = 0.f, q = 0.f;
#pragma unroll
        for (int w = 0; w < 8; ++w) { s += sm_s[w]; q += sm_q[w]; }
        const float invn = 1.f / (float)BHW;
        float mean = s * invn;
        float var  = q * invn - mean*mean;
        g_mean[c] = mean;
        g_inv[c]  = rsqrtf(var + EPSV);
    }
}

// ---------------- kernel 5: residual + affine (float4 vectorized) ----------
__global__ __launch_bounds__(256) void out_kernel(
    const float* __restrict__ x, const float* __restrict__ gamma,
    const float* __restrict__ beta, float* __restrict__ out)
{
    int i4  = blockIdx.x * 256 + threadIdx.x;   // 1,048,576 float4's
    int idx = i4 * 4;
    int c   = (idx >> 12) & 255;                 // constant across the 4 lanes
    float mean = g_mean[c], inv = g_inv[c];
    float gm = gamma[c], bt = beta[c];
    float4 yv = *(const float4*)(g_y + idx);
    float4 xv = *(const float4*)(x + idx);
    float4 o;
    o.x = xv.x + gm * ((yv.x - mean) * inv) + bt;
    o.y = xv.y + gm * ((yv.y - mean) * inv) + bt;
    o.z = xv.z + gm * ((yv.z - mean) * inv) + bt;
    o.w = xv.w + gm * ((yv.w - mean) * inv) + bt;
    *(float4*)(out + idx) = o;
}

// ---------------------------------------------------------------------------
extern "C" void kernel_launch(void* const* d_in, const int* in_sizes, int n_in,
                              void* d_out, int out_size)
{
    const float* x      = (const float*)d_in[0];
    const float* vessel = (const float*)d_in[1];
    const float* wk     = (const float*)d_in[2];
    const float* bk     = (const float*)d_in[3];
    const float* wq     = (const float*)d_in[4];
    const float* bq     = (const float*)d_in[5];
    const float* wx     = (const float*)d_in[6];
    const float* bx     = (const float*)d_in[7];
    const float* wf     = (const float*)d_in[8];
    const float* bf     = (const float*)d_in[9];
    const float* gamma  = (const float*)d_in[10];
    const float* beta   = (const float*)d_in[11];
    float* out          = (float*)d_out;

    qkx_kernel<<<dim3(BHW/256, 3), 256>>>(x, vessel, wk, bk, wq, bq, wx, bx);
    score_kernel<<<dim3(BHW/256, 9), 256>>>();
    softmax_kernel<<<BHW/64, 64>>>();
    apply_kernel<<<BHW/32, 256>>>();
    convf_kernel<<<BHW/32, 256>>>(wf, bf);
    stats_kernel<<<Cn, 256>>>();
    out_kernel<<<Bn*Cn*HW/1024, 256>>>(x, gamma, beta, out);
}

// round 12
// speedup vs baseline: 1.9453x; 1.0471x over previous
#include <cuda_runtime.h>

#define Bn   4
#define Cn   256
#define CPn  32
#define Hn   64
#define Wn   64
#define HW   (Hn*Wn)          // 4096
#define BHW  (Bn*HW)          // 16384
#define EPSV 1e-5f

// ---------------- scratch (device globals: no allocation allowed) ----------
__device__ __align__(16) float g_k[BHW*CPn];     // key map  (pixel-major)
__device__ __align__(16) float g_q[BHW*CPn];     // query map
__device__ __align__(16) float g_x[BHW*CPn];     // value map
__device__ __align__(16) float g_s[81*BHW];      // scores -> combined weights
__device__ __align__(16) float g_pre[BHW*CPn];   // attention output
__device__ __align__(16) float g_y[Bn*Cn*HW];    // conv-f output (channel-major)
__device__ float g_mean[Cn], g_inv[Cn];

// ---------------- packed f32x2 helpers (FFMA2: PTX-only pattern) -----------
__device__ __forceinline__ unsigned long long pk2(float lo, float hi) {
    unsigned long long r;
    asm("mov.b64 %0, {%1, %2};" : "=l"(r) : "f"(lo), "f"(hi));
    return r;
}
__device__ __forceinline__ void fma2(unsigned long long& d,
                                     unsigned long long a, unsigned long long b) {
    asm("fma.rn.f32x2 %0, %1, %2, %0;" : "+l"(d) : "l"(a), "l"(b));
}
__device__ __forceinline__ void upk2(unsigned long long v, float& lo, float& hi) {
    asm("mov.b64 {%0, %1}, %2;" : "=f"(lo), "=f"(hi) : "l"(v));
}

// ---------------- kernel 1: km/qm/xm 1x1 convs (256 -> 32), pixel-major ----
__global__ __launch_bounds__(256) void qkx_kernel(
    const float* __restrict__ x,  const float* __restrict__ vessel,
    const float* __restrict__ wk, const float* __restrict__ bk,
    const float* __restrict__ wq, const float* __restrict__ bq,
    const float* __restrict__ wx, const float* __restrict__ bx)
{
    __shared__ float ws[Cn*CPn];          // transposed: ws[c*32+o]
    const int map = blockIdx.y;
    const float* __restrict__ w    = (map == 0) ? wk : (map == 1) ? wq : wx;
    const float* __restrict__ bias = (map == 0) ? bk : (map == 1) ? bq : bx;
    float* __restrict__ out        = (map == 0) ? g_k : (map == 1) ? g_q : g_x;

    const int tid = threadIdx.x;
    for (int i = tid; i < Cn*CPn; i += 256) {      // coalesced read of w[o][c]
        int o = i >> 8, c = i & 255;
        ws[c*CPn + o] = w[i];
    }
    __syncthreads();

    const int p  = blockIdx.x * 256 + tid;         // global pixel
    const int b  = p >> 12, hw = p & 4095;
    const float* __restrict__ xp = x + (size_t)b*Cn*HW + hw;

    unsigned long long acc2[16];
#pragma unroll
    for (int j = 0; j < 16; ++j) acc2[j] = 0ULL;

#pragma unroll 8
    for (int c = 0; c < Cn; ++c) {
        float xv = __ldg(xp + c*HW);
        unsigned long long xv2 = pk2(xv, xv);
        const unsigned long long* w2 = (const unsigned long long*)(ws + c*CPn);
#pragma unroll
        for (int j = 0; j < 16; ++j) fma2(acc2[j], w2[j], xv2);
    }

    const float scale = (map == 0) ? vessel[p] : 1.f;
    float4* op = (float4*)(out + (size_t)p*CPn);
#pragma unroll
    for (int j = 0; j < 8; ++j) {
        float a0, a1, a2, a3;
        upk2(acc2[2*j],   a0, a1);
        upk2(acc2[2*j+1], a2, a3);
        float4 v;
        v.x = (a0 + bias[4*j+0]) * scale;
        v.y = (a1 + bias[4*j+1]) * scale;
        v.z = (a2 + bias[4*j+2]) * scale;
        v.w = (a3 + bias[4*j+3]) * scale;
        op[j] = v;
    }
}

// ---------------- kernel 2a: scores (branch-free clamped loads) ------------
// thread = (pixel, dy). Computes 9 scores (dx = -4..4). OOB -> select 0.
__global__ __launch_bounds__(256) void score_kernel()
{
    const int dyi = blockIdx.y;                    // 0..8
    const int p   = blockIdx.x * 256 + threadIdx.x;
    const int b   = p >> 12, hw = p & 4095;
    const int y   = hw >> 6, x = hw & 63;
    const int yy  = y + dyi - 4;
    const bool yok = (unsigned)yy < (unsigned)Hn;
    const int yyc = min(max(yy, 0), Hn - 1);       // clamped (always valid)

    const float4* qp = (const float4*)(g_q + (size_t)p*CPn);
    float4 q[8];
#pragma unroll
    for (int j = 0; j < 8; ++j) q[j] = qp[j];

    const float* __restrict__ krow = g_k + ((size_t)b*HW + (size_t)yyc*Wn)*CPn;

#pragma unroll
    for (int dxi = 0; dxi < 9; ++dxi) {
        int xx  = x + dxi - 4;
        bool ok = yok && (unsigned)xx < (unsigned)Wn;
        int xxc = min(max(xx, 0), Wn - 1);
        const float4* kp = (const float4*)(krow + (size_t)xxc*CPn);
        float s = 0.f;
#pragma unroll
        for (int j = 0; j < 8; ++j) {
            float4 kv = kp[j];
            s += kv.x*q[j].x + kv.y*q[j].y + kv.z*q[j].z + kv.w*q[j].w;
        }
        g_s[(size_t)(dyi*9 + dxi)*BHW + p] = ok ? s : 0.f;
    }
}

// ---------------- kernel 2b: nested-window softmax -> combined weights -----
__global__ __launch_bounds__(64) void softmax_kernel()
{
    const int p = blockIdx.x * 64 + threadIdx.x;

    float s[81];
#pragma unroll
    for (int i = 0; i < 81; ++i) s[i] = g_s[(size_t)i*BHW + p];

    float m = s[0];
#pragma unroll
    for (int i = 1; i < 81; ++i) m = fmaxf(m, s[i]);

    float S9 = 0.f, S7 = 0.f, S5 = 0.f, S3 = 0.f;
#pragma unroll
    for (int iy = 0; iy < 9; ++iy) {
#pragma unroll
        for (int ix = 0; ix < 9; ++ix) {
            int i = iy*9 + ix;
            float ev = __expf(s[i] - m);
            s[i] = ev;
            S9 += ev;
            if (iy >= 1 && iy <= 7 && ix >= 1 && ix <= 7) S7 += ev;
            if (iy >= 2 && iy <= 6 && ix >= 2 && ix <= 6) S5 += ev;
            if (iy >= 3 && iy <= 5 && ix >= 3 && ix <= 5) S3 += ev;
        }
    }
    const float r9 = 1.f/S9, r7 = 1.f/S7, r5 = 1.f/S5, r3 = 1.f/S3;
#pragma unroll
    for (int iy = 0; iy < 9; ++iy) {
#pragma unroll
        for (int ix = 0; ix < 9; ++ix) {
            int i = iy*9 + ix;
            float cf = r9;
            if (iy >= 1 && iy <= 7 && ix >= 1 && ix <= 7) cf += r7;
            if (iy >= 2 && iy <= 6 && ix >= 2 && ix <= 6) cf += r5;
            if (iy >= 3 && iy <= 5 && ix >= 3 && ix <= 5) cf += r3;
            g_s[(size_t)i*BHW + p] = s[i] * cf;
        }
    }
}

// ---------------- kernel 2c: apply weights (branch-free clamped loads) -----
// thread = (pixel, group of 4 channels). 32 px x 8 groups per block.
__global__ __launch_bounds__(256) void apply_kernel()
{
    const int tid = threadIdx.x;
    const int g   = tid & 7;                  // channel group (4 ch)
    const int p   = blockIdx.x * 32 + (tid >> 3);
    const int b   = p >> 12, hw = p & 4095;
    const int y   = hw >> 6, x = hw & 63;

    const float* __restrict__ xb = g_x + (size_t)b*HW*CPn + g*4;

    float acc0 = 0.f, acc1 = 0.f, acc2 = 0.f, acc3 = 0.f;

#pragma unroll
    for (int dyi = 0; dyi < 9; ++dyi) {
        int yy  = y + dyi - 4;
        bool yok = (unsigned)yy < (unsigned)Hn;
        int yyc = min(max(yy, 0), Hn - 1);
        const float* rowp = xb + (size_t)(yyc*Wn)*CPn;
        const float* wrow = g_s + (size_t)(dyi*9)*BHW + p;
#pragma unroll
        for (int dxi = 0; dxi < 9; ++dxi) {
            int xx  = x + dxi - 4;
            bool ok = yok && (unsigned)xx < (unsigned)Wn;
            int xxc = min(max(xx, 0), Wn - 1);
            float w   = wrow[(size_t)dxi*BHW];          // unconditional load
            float wgt = ok ? w : 0.f;                    // FSEL, no branch
            float4 a = *(const float4*)(rowp + (size_t)xxc*CPn);  // unconditional
            acc0 += wgt*a.x; acc1 += wgt*a.y;
            acc2 += wgt*a.z; acc3 += wgt*a.w;
        }
    }
    *(float4*)(g_pre + (size_t)p*CPn + g*4) = make_float4(acc0, acc1, acc2, acc3);
}

// ---------------- kernel 3: conv-f (32->256), no stats ---------------------
__global__ __launch_bounds__(256) void convf_kernel(
    const float* __restrict__ wf, const float* __restrict__ bf)
{
    __shared__ float wf_s[Cn*CPn];      // 32 KB, [c][k]
    __shared__ float pre_s[32*33];      // pitch-33: conflict-free

    const int tid = threadIdx.x;
    const int pl  = tid & 31;
    const int g   = tid >> 5;           // 0..7
    const int p0  = blockIdx.x * 32;
    const int b   = p0 >> 12;
    const int hw  = (p0 & 4095) + pl;

    for (int i = tid; i < Cn*CPn; i += 256) wf_s[i] = wf[i];
    for (int i = tid; i < 32*CPn; i += 256) {
        int pli = i >> 5, j = i & 31;
        pre_s[pli*33 + j] = g_pre[(size_t)(p0 + pli)*CPn + j];
    }
    __syncthreads();

    unsigned long long pv2[16];
#pragma unroll
    for (int j = 0; j < 16; ++j)
        pv2[j] = pk2(pre_s[pl*33 + 2*j], pre_s[pl*33 + 2*j + 1]);

#pragma unroll 1
    for (int j = 0; j < 32; ++j) {
        const int c = g*32 + j;
        const unsigned long long* w2 = (const unsigned long long*)(wf_s + c*CPn);
        unsigned long long a2 = 0ULL;
#pragma unroll
        for (int q4 = 0; q4 < 16; ++q4) fma2(a2, w2[q4], pv2[q4]);
        float lo, hi; upk2(a2, lo, hi);
        g_y[((size_t)(b*Cn + c))*HW + hw] = bf[c] + lo + hi;  // coalesced per warp
    }
}

// ---------------- kernel 4: BN stats (one block per channel, no atomics) ---
__global__ __launch_bounds__(256) void stats_kernel()
{
    __shared__ float sm_s[8], sm_q[8];
    const int c   = blockIdx.x;
    const int tid = threadIdx.x;

    float sum = 0.f, sq = 0.f;
#pragma unroll
    for (int b = 0; b < Bn; ++b) {
        const float* __restrict__ yp = g_y + ((size_t)(b*Cn + c))*HW;
        for (int i = tid; i < HW; i += 256) {
            float v = yp[i];
            sum += v; sq += v*v;
        }
    }
#pragma unroll
    for (int off = 16; off; off >>= 1) {
        sum += __shfl_xor_sync(0xFFFFFFFFu, sum, off);
        sq  += __shfl_xor_sync(0xFFFFFFFFu, sq,  off);
    }
    if ((tid & 31) == 0) { sm_s[tid >> 5] = sum; sm_q[tid >> 5] = sq; }
    __syncthreads();
    if (tid == 0) {
        float s = 0.f, q = 0.f;
#pragma unroll
        for (int w = 0; w < 8; ++w) { s += sm_s[w]; q += sm_q[w]; }
        const float invn = 1.f / (float)BHW;
        float mean = s * invn;
        float var  = q * invn - mean*mean;
        g_mean[c] = mean;
        g_inv[c]  = rsqrtf(var + EPSV);
    }
}

// ---------------- kernel 5: residual + affine (float4 vectorized) ----------
__global__ __launch_bounds__(256) void out_kernel(
    const float* __restrict__ x, const float* __restrict__ gamma,
    const float* __restrict__ beta, float* __restrict__ out)
{
    int i4  = blockIdx.x * 256 + threadIdx.x;   // 1,048,576 float4's
    int idx = i4 * 4;
    int c   = (idx >> 12) & 255;                 // constant across the 4 lanes
    float mean = g_mean[c], inv = g_inv[c];
    float gm = gamma[c], bt = beta[c];
    float4 yv = *(const float4*)(g_y + idx);
    float4 xv = *(const float4*)(x + idx);
    float4 o;
    o.x = xv.x + gm * ((yv.x - mean) * inv) + bt;
    o.y = xv.y + gm * ((yv.y - mean) * inv) + bt;
    o.z = xv.z + gm * ((yv.z - mean) * inv) + bt;
    o.w = xv.w + gm * ((yv.w - mean) * inv) + bt;
    *(float4*)(out + idx) = o;
}

// ---------------------------------------------------------------------------
extern "C" void kernel_launch(void* const* d_in, const int* in_sizes, int n_in,
                              void* d_out, int out_size)
{
    const float* x      = (const float*)d_in[0];
    const float* vessel = (const float*)d_in[1];
    const float* wk     = (const float*)d_in[2];
    const float* bk     = (const float*)d_in[3];
    const float* wq     = (const float*)d_in[4];
    const float* bq     = (const float*)d_in[5];
    const float* wx     = (const float*)d_in[6];
    const float* bx     = (const float*)d_in[7];
    const float* wf     = (const float*)d_in[8];
    const float* bf     = (const float*)d_in[9];
    const float* gamma  = (const float*)d_in[10];
    const float* beta   = (const float*)d_in[11];
    float* out          = (float*)d_out;

    qkx_kernel<<<dim3(BHW/256, 3), 256>>>(x, vessel, wk, bk, wq, bq, wx, bx);
    score_kernel<<<dim3(BHW/256, 9), 256>>>();
    softmax_kernel<<<BHW/64, 64>>>();
    apply_kernel<<<BHW/32, 256>>>();
    convf_kernel<<<BHW/32, 256>>>(wf, bf);
    stats_kernel<<<Cn, 256>>>();
    out_kernel<<<Bn*Cn*HW/1024, 256>>>(x, gamma, beta, out);
}

// round 17
// speedup vs baseline: 2.2910x; 1.1777x over previous
#include <cuda_runtime.h>

#define Bn   4
#define Cn   256
#define CPn  32
#define Hn   64
#define Wn   64
#define HW   (Hn*Wn)          // 4096
#define BHW  (Bn*HW)          // 16384
#define EPSV 1e-5f

// ---------------- scratch (device globals: no allocation allowed) ----------
__device__ __align__(16) float g_k[BHW*CPn];     // key map  (pixel-major)
__device__ __align__(16) float g_q[BHW*CPn];     // query map
__device__ __align__(16) float g_x[BHW*CPn];     // value map
__device__ __align__(16) float g_s[81*BHW];      // scores -> combined weights
__device__ __align__(16) float g_pre[BHW*CPn];   // attention output
__device__ __align__(16) float g_y[Bn*Cn*HW];    // conv-f output (channel-major)
__device__ float g_mean[Cn], g_inv[Cn];

// ---------------- packed f32x2 helpers (FFMA2: PTX-only pattern) -----------
__device__ __forceinline__ unsigned long long pk2(float lo, float hi) {
    unsigned long long r;
    asm("mov.b64 %0, {%1, %2};" : "=l"(r) : "f"(lo), "f"(hi));
    return r;
}
__device__ __forceinline__ void fma2(unsigned long long& d,
                                     unsigned long long a, unsigned long long b) {
    asm("fma.rn.f32x2 %0, %1, %2, %0;" : "+l"(d) : "l"(a), "l"(b));
}
__device__ __forceinline__ void upk2(unsigned long long v, float& lo, float& hi) {
    asm("mov.b64 {%0, %1}, %2;" : "=f"(lo), "=f"(hi) : "l"(v));
}

// ---------------- kernel 1: km/qm/xm 1x1 convs (256 -> 32), pixel-major ----
__global__ __launch_bounds__(256) void qkx_kernel(
    const float* __restrict__ x,  const float* __restrict__ vessel,
    const float* __restrict__ wk, const float* __restrict__ bk,
    const float* __restrict__ wq, const float* __restrict__ bq,
    const float* __restrict__ wx, const float* __restrict__ bx)
{
    __shared__ float ws[Cn*CPn];          // transposed: ws[c*32+o]
    const int map = blockIdx.y;
    const float* __restrict__ w    = (map == 0) ? wk : (map == 1) ? wq : wx;
    const float* __restrict__ bias = (map == 0) ? bk : (map == 1) ? bq : bx;
    float* __restrict__ out        = (map == 0) ? g_k : (map == 1) ? g_q : g_x;

    const int tid = threadIdx.x;
    for (int i = tid; i < Cn*CPn; i += 256) {      // coalesced read of w[o][c]
        int o = i >> 8, c = i & 255;
        ws[c*CPn + o] = w[i];
    }
    __syncthreads();

    const int p  = blockIdx.x * 256 + tid;         // global pixel
    const int b  = p >> 12, hw = p & 4095;
    const float* __restrict__ xp = x + (size_t)b*Cn*HW + hw;

    unsigned long long acc2[16];
#pragma unroll
    for (int j = 0; j < 16; ++j) acc2[j] = 0ULL;

#pragma unroll 8
    for (int c = 0; c < Cn; ++c) {
        float xv = __ldg(xp + c*HW);
        unsigned long long xv2 = pk2(xv, xv);
        const unsigned long long* w2 = (const unsigned long long*)(ws + c*CPn);
#pragma unroll
        for (int j = 0; j < 16; ++j) fma2(acc2[j], w2[j], xv2);
    }

    const float scale = (map == 0) ? vessel[p] : 1.f;
    float4* op = (float4*)(out + (size_t)p*CPn);
#pragma unroll
    for (int j = 0; j < 8; ++j) {
        float a0, a1, a2, a3;
        upk2(acc2[2*j],   a0, a1);
        upk2(acc2[2*j+1], a2, a3);
        float4 v;
        v.x = (a0 + bias[4*j+0]) * scale;
        v.y = (a1 + bias[4*j+1]) * scale;
        v.z = (a2 + bias[4*j+2]) * scale;
        v.w = (a3 + bias[4*j+3]) * scale;
        op[j] = v;
    }
}

// ---------------- kernel 2a: scores, pixel-pair version --------------------
// thread = (pixel-pair, dy): 10 k-loads -> 18 dot products. OOB -> 0 store.
__global__ __launch_bounds__(256) void score_kernel()
{
    const int dyi = blockIdx.y;                         // 0..8
    const int t   = blockIdx.x * 256 + threadIdx.x;     // pair index
    const int p0  = 2*t;
    const int b   = p0 >> 12, hw = p0 & 4095;
    const int y   = hw >> 6, x0 = hw & 63;              // x0 even
    const int yy  = y + dyi - 4;
    const bool yok = (unsigned)yy < (unsigned)Hn;
    const int yyc = min(max(yy, 0), Hn - 1);

    float4 q0[8], q1[8];
    {
        const float4* qp0 = (const float4*)(g_q + (size_t)p0*CPn);
        const float4* qp1 = (const float4*)(g_q + (size_t)(p0+1)*CPn);
#pragma unroll
        for (int j = 0; j < 8; ++j) { q0[j] = qp0[j]; q1[j] = qp1[j]; }
    }

    const float* __restrict__ krow = g_k + ((size_t)b*HW + (size_t)yyc*Wn)*CPn;

    float s0[9], s1[9];
#pragma unroll
    for (int j = 0; j < 9; ++j) { s0[j] = 0.f; s1[j] = 0.f; }

#pragma unroll
    for (int j = 0; j < 10; ++j) {                      // absolute x = x0-4+j
        int xa  = x0 - 4 + j;
        int xac = min(max(xa, 0), Wn - 1);
        const float4* kp = (const float4*)(krow + (size_t)xac*CPn);
        float d0 = 0.f, d1 = 0.f;
#pragma unroll
        for (int c4 = 0; c4 < 8; ++c4) {
            float4 kv = kp[c4];
            d0 += kv.x*q0[c4].x + kv.y*q0[c4].y + kv.z*q0[c4].z + kv.w*q0[c4].w;
            d1 += kv.x*q1[c4].x + kv.y*q1[c4].y + kv.z*q1[c4].z + kv.w*q1[c4].w;
        }
        if (j < 9) s0[j]   = d0;                        // px0, dxi = j
        if (j >= 1) s1[j-1] = d1;                       // px1, dxi = j-1
    }

#pragma unroll
    for (int dxi = 0; dxi < 9; ++dxi) {
        bool ok0 = yok && (unsigned)(x0 - 4 + dxi) < (unsigned)Wn;
        bool ok1 = yok && (unsigned)(x0 - 3 + dxi) < (unsigned)Wn;
        float2 v;
        v.x = ok0 ? s0[dxi] : 0.f;
        v.y = ok1 ? s1[dxi] : 0.f;
        *(float2*)(g_s + (size_t)(dyi*9 + dxi)*BHW + p0) = v;   // coalesced
    }
}

// ---------------- kernel 2b: nested-window softmax -> combined weights -----
__global__ __launch_bounds__(64) void softmax_kernel()
{
    const int p = blockIdx.x * 64 + threadIdx.x;

    float s[81];
#pragma unroll
    for (int i = 0; i < 81; ++i) s[i] = g_s[(size_t)i*BHW + p];

    float m = s[0];
#pragma unroll
    for (int i = 1; i < 81; ++i) m = fmaxf(m, s[i]);

    float S9 = 0.f, S7 = 0.f, S5 = 0.f, S3 = 0.f;
#pragma unroll
    for (int iy = 0; iy < 9; ++iy) {
#pragma unroll
        for (int ix = 0; ix < 9; ++ix) {
            int i = iy*9 + ix;
            float ev = __expf(s[i] - m);
            s[i] = ev;
            S9 += ev;
            if (iy >= 1 && iy <= 7 && ix >= 1 && ix <= 7) S7 += ev;
            if (iy >= 2 && iy <= 6 && ix >= 2 && ix <= 6) S5 += ev;
            if (iy >= 3 && iy <= 5 && ix >= 3 && ix <= 5) S3 += ev;
        }
    }
    const float r9 = 1.f/S9, r7 = 1.f/S7, r5 = 1.f/S5, r3 = 1.f/S3;
#pragma unroll
    for (int iy = 0; iy < 9; ++iy) {
#pragma unroll
        for (int ix = 0; ix < 9; ++ix) {
            int i = iy*9 + ix;
            float cf = r9;
            if (iy >= 1 && iy <= 7 && ix >= 1 && ix <= 7) cf += r7;
            if (iy >= 2 && iy <= 6 && ix >= 2 && ix <= 6) cf += r5;
            if (iy >= 3 && iy <= 5 && ix >= 3 && ix <= 5) cf += r3;
            g_s[(size_t)i*BHW + p] = s[i] * cf;
        }
    }
}

// ---------------- kernel 2c: apply, pixel-pair version ---------------------
// thread = (pixel-pair, 4-ch group): 10 value loads -> contributions for
// both pixels. x-clamps hoisted out of the row loop.
__global__ __launch_bounds__(256) void apply_kernel()
{
    const int tid = threadIdx.x;
    const int g   = tid & 7;                         // 4-ch group
    const int t   = blockIdx.x * 32 + (tid >> 3);    // pair index
    const int p0  = 2*t;
    const int b   = p0 >> 12, hw = p0 & 4095;
    const int y   = hw >> 6, x0 = hw & 63;

    // hoisted per-j x info (dyi-invariant)
    int  xoff[10];                                   // clamped offset in floats
    bool okx[10];
#pragma unroll
    for (int j = 0; j < 10; ++j) {
        int xa  = x0 - 4 + j;
        okx[j]  = (unsigned)xa < (unsigned)Wn;
        xoff[j] = min(max(xa, 0), Wn - 1) * CPn;
    }

    const float* __restrict__ xb = g_x + (size_t)b*HW*CPn + g*4;

    float a00 = 0.f, a01 = 0.f, a02 = 0.f, a03 = 0.f;   // px0
    float a10 = 0.f, a11 = 0.f, a12 = 0.f, a13 = 0.f;   // px1

#pragma unroll
    for (int dyi = 0; dyi < 9; ++dyi) {
        int yy  = y + dyi - 4;
        bool yok = (unsigned)yy < (unsigned)Hn;
        int yyc = min(max(yy, 0), Hn - 1);
        const float* rowp = xb + (size_t)(yyc*Wn)*CPn;
        const float* wrow = g_s + (size_t)(dyi*9)*BHW + p0;

        float2 wp[9];
#pragma unroll
        for (int dxi = 0; dxi < 9; ++dxi)
            wp[dxi] = *(const float2*)(wrow + (size_t)dxi*BHW);  // coalesced

#pragma unroll
        for (int j = 0; j < 10; ++j) {
            bool ok = yok && okx[j];
            float4 a = *(const float4*)(rowp + xoff[j]);         // unconditional
            float w0 = (j < 9 && ok) ? wp[j].x   : 0.f;          // px0, dxi=j
            float w1 = (j >= 1 && ok) ? wp[j-1].y : 0.f;         // px1, dxi=j-1
            a00 += w0*a.x; a01 += w0*a.y; a02 += w0*a.z; a03 += w0*a.w;
            a10 += w1*a.x; a11 += w1*a.y; a12 += w1*a.z; a13 += w1*a.w;
        }
    }
    *(float4*)(g_pre + (size_t)p0*CPn     + g*4) = make_float4(a00, a01, a02, a03);
    *(float4*)(g_pre + (size_t)(p0+1)*CPn + g*4) = make_float4(a10, a11, a12, a13);
}

// ---------------- kernel 3: conv-f (32->256), no stats ---------------------
__global__ __launch_bounds__(256) void convf_kernel(
    const float* __restrict__ wf, const float* __restrict__ bf)
{
    __shared__ float wf_s[Cn*CPn];      // 32 KB, [c][k]
    __shared__ float pre_s[32*33];      // pitch-33: conflict-free

    const int tid = threadIdx.x;
    const int pl  = tid & 31;
    const int g   = tid >> 5;           // 0..7
    const int p0  = blockIdx.x * 32;
    const int b   = p0 >> 12;
    const int hw  = (p0 & 4095) + pl;

    for (int i = tid; i < Cn*CPn; i += 256) wf_s[i] = wf[i];
    for (int i = tid; i < 32*CPn; i += 256) {
        int pli = i >> 5, j = i & 31;
        pre_s[pli*33 + j] = g_pre[(size_t)(p0 + pli)*CPn + j];
    }
    __syncthreads();

    unsigned long long pv2[16];
#pragma unroll
    for (int j = 0; j < 16; ++j)
        pv2[j] = pk2(pre_s[pl*33 + 2*j], pre_s[pl*33 + 2*j + 1]);

#pragma unroll 1
    for (int j = 0; j < 32; ++j) {
        const int c = g*32 + j;
        const unsigned long long* w2 = (const unsigned long long*)(wf_s + c*CPn);
        unsigned long long a2 = 0ULL;
#pragma unroll
        for (int q4 = 0; q4 < 16; ++q4) fma2(a2, w2[q4], pv2[q4]);
        float lo, hi; upk2(a2, lo, hi);
        g_y[((size_t)(b*Cn + c))*HW + hw] = bf[c] + lo + hi;  // coalesced per warp
    }
}

// ---------------- kernel 4: BN stats (one block per channel, no atomics) ---
__global__ __launch_bounds__(256) void stats_kernel()
{
    __shared__ float sm_s[8], sm_q[8];
    const int c   = blockIdx.x;
    const int tid = threadIdx.x;

    float sum = 0.f, sq = 0.f;
#pragma unroll
    for (int b = 0; b < Bn; ++b) {
        const float* __restrict__ yp = g_y + ((size_t)(b*Cn + c))*HW;
        for (int i = tid; i < HW; i += 256) {
            float v = yp[i];
            sum += v; sq += v*v;
        }
    }
#pragma unroll
    for (int off = 16; off; off >>= 1) {
        sum += __shfl_xor_sync(0xFFFFFFFFu, sum, off);
        sq  += __shfl_xor_sync(0xFFFFFFFFu, sq,  off);
    }
    if ((tid & 31) == 0) { sm_s[tid >> 5] = sum; sm_q[tid >> 5] = sq; }
    __syncthreads();
    if (tid == 0) {
        float s = 0.f, q = 0.f;
#pragma unroll
        for (int w = 0; w < 8; ++w) { s += sm_s[w]; q += sm_q[w]; }
        const float invn = 1.f / (float)BHW;
        float mean = s * invn;
        float var  = q * invn - mean*mean;
        g_mean[c] = mean;
        g_inv[c]  = rsqrtf(var + EPSV);
    }
}

// ---------------- kernel 5: residual + affine (float4 vectorized) ----------
__global__ __launch_bounds__(256) void out_kernel(
    const float* __restrict__ x, const float* __restrict__ gamma,
    const float* __restrict__ beta, float* __restrict__ out)
{
    int i4  = blockIdx.x * 256 + threadIdx.x;   // 1,048,576 float4's
    int idx = i4 * 4;
    int c   = (idx >> 12) & 255;                 // constant across the 4 lanes
    float mean = g_mean[c], inv = g_inv[c];
    float gm = gamma[c], bt = beta[c];
    float4 yv = *(const float4*)(g_y + idx);
    float4 xv = *(const float4*)(x + idx);
    float4 o;
    o.x = xv.x + gm * ((yv.x - mean) * inv) + bt;
    o.y = xv.y + gm * ((yv.y - mean) * inv) + bt;
    o.z = xv.z + gm * ((yv.z - mean) * inv) + bt;
    o.w = xv.w + gm * ((yv.w - mean) * inv) + bt;
    *(float4*)(out + idx) = o;
}

// ---------------------------------------------------------------------------
extern "C" void kernel_launch(void* const* d_in, const int* in_sizes, int n_in,
                              void* d_out, int out_size)
{
    const float* x      = (const float*)d_in[0];
    const float* vessel = (const float*)d_in[1];
    const float* wk     = (const float*)d_in[2];
    const float* bk     = (const float*)d_in[3];
    const float* wq     = (const float*)d_in[4];
    const float* bq     = (const float*)d_in[5];
    const float* wx     = (const float*)d_in[6];
    const float* bx     = (const float*)d_in[7];
    const float* wf     = (const float*)d_in[8];
    const float* bf     = (const float*)d_in[9];
    const float* gamma  = (const float*)d_in[10];
    const float* beta   = (const float*)d_in[11];
    float* out          = (float*)d_out;

    qkx_kernel<<<dim3(BHW/256, 3), 256>>>(x, vessel, wk, bk, wq, bq, wx, bx);
    score_kernel<<<dim3(BHW/2/256, 9), 256>>>();
    softmax_kernel<<<BHW/64, 64>>>();
    apply_kernel<<<BHW/2/32, 256>>>();
    convf_kernel<<<BHW/32, 256>>>(wf, bf);
    stats_kernel<<<Cn, 256>>>();
    out_kernel<<<Bn*Cn*HW/1024, 256>>>(x, gamma, beta, out);
}